// round 15
// baseline (speedup 1.0000x reference)
#include <cuda_runtime.h>
#include <cuda_fp16.h>
#include <cstdio>
#include <cstdint>

#define N_MAX 50000
#define E_MAX 800000
#define H 128
#define PAD 80

// -------- scratch (device globals; no allocation allowed) --------
__device__ unsigned           g_zh1[(size_t)N_MAX * 64];   // fp16x2 layer-1 out
__device__ unsigned           g_zh2[(size_t)N_MAX * 64];   // fp16x2 layer-2 out
__device__ unsigned           g_aggh[(size_t)N_MAX * 64];  // fp16x2 aggregated
__device__ unsigned           g_wp[8 * 8192];              // half2-packed weights [(2L+2) x 64 x 128]
__device__ float              g_ew[4 * H];
__device__ float              g_er[4 * H];
__device__ int                g_csr_pad[(size_t)N_MAX * PAD];
__device__ unsigned long long g_meta[N_MAX];   // [0:8)=deg, [8:16)=cnt0 ... [32:40)=cnt3

// -------- helpers --------
__device__ __forceinline__ uint32_t pack_h2(float lo, float hi) {
    __half2 h = __floats2half2_rn(lo, hi);
    return *reinterpret_cast<uint32_t*>(&h);
}
__device__ __forceinline__ float4 h4_to_f4(uint2 v) {
    __half2 a = *reinterpret_cast<__half2*>(&v.x);
    __half2 b = *reinterpret_cast<__half2*>(&v.y);
    float2 fa = __half22float2(a);
    float2 fb = __half22float2(b);
    return make_float4(fa.x, fa.y, fb.x, fb.y);
}
__device__ __forceinline__ uint32_t hadd2u(uint32_t a, uint32_t b) {
    uint32_t r;
    asm("add.rn.f16x2 %0, %1, %2;" : "=r"(r) : "r"(a), "r"(b));
    return r;
}
__device__ __forceinline__ uint4 hadd2x4(uint4 a, uint4 b) {
    return make_uint4(hadd2u(a.x, b.x), hadd2u(a.y, b.y),
                      hadd2u(a.z, b.z), hadd2u(a.w, b.w));
}
__device__ __forceinline__ void h8_acc(float* acc, uint4 d) {
    float2 f0 = __half22float2(*reinterpret_cast<__half2*>(&d.x));
    float2 f1 = __half22float2(*reinterpret_cast<__half2*>(&d.y));
    float2 f2 = __half22float2(*reinterpret_cast<__half2*>(&d.z));
    float2 f3 = __half22float2(*reinterpret_cast<__half2*>(&d.w));
    acc[0] += f0.x; acc[1] += f0.y; acc[2] += f1.x; acc[3] += f1.y;
    acc[4] += f2.x; acc[5] += f2.y; acc[6] += f3.x; acc[7] += f3.y;
}

__device__ __forceinline__ void mma_f16(float c[4], const unsigned a[4], const unsigned b[2]) {
    asm volatile(
        "mma.sync.aligned.m16n8k16.row.col.f32.f16.f16.f32 "
        "{%0,%1,%2,%3}, {%4,%5,%6,%7}, {%8,%9}, {%0,%1,%2,%3};\n"
        : "+f"(c[0]), "+f"(c[1]), "+f"(c[2]), "+f"(c[3])
        : "r"(a[0]), "r"(a[1]), "r"(a[2]), "r"(a[3]), "r"(b[0]), "r"(b[1]));
}

__device__ __forceinline__ uint32_t smem_u32(const void* p) {
    uint32_t a;
    asm("{ .reg .u64 t; cvta.to.shared.u64 t, %1; cvt.u32.u64 %0, t; }" : "=r"(a) : "l"(p));
    return a;
}
#define CP_ASYNC16(dst_u32, src_ptr, szbytes) \
    asm volatile("cp.async.cg.shared.global [%0], [%1], 16, %2;" \
        :: "r"(dst_u32), "l"(src_ptr), "r"(szbytes))
#define CP_COMMIT() asm volatile("cp.async.commit_group;" ::: "memory")
#define CP_WAIT(nn)  asm volatile("cp.async.wait_group %0;" :: "n"(nn) : "memory")

// -------- fused prep: [0,wpb) pack weights | [wpb,wpb+8) EW/ER | rest zero meta --------
__global__ void prep_kernel(const float* __restrict__ Wout, const float* __restrict__ Wroot,
                            const float* __restrict__ w1,
                            unsigned* __restrict__ wp, int L,
                            const float* __restrict__ emb,
                            float* __restrict__ ew, float* __restrict__ er,
                            unsigned long long* __restrict__ meta,
                            int n, int wpb) {
    int b = blockIdx.x;
    int tid = threadIdx.x;
    if (b < wpb) {
        int i = b * 256 + tid;
        int total = (2 * L + 2) * 8192;
        if (i < total) {
            int m  = i >> 13;
            int w  = i & 8191;
            int k2 = w >> 7;
            int nn = w & 127;
            const float* src;
            if (m < L)           src = Wout + (size_t)m * (H * H);
            else if (m < 2 * L)  src = Wroot + (size_t)(m - L) * (H * H);
            else if (m == 2 * L) src = w1;
            else                 src = w1 + (size_t)H * H;
            float lo = src[(2 * k2) * H + nn];
            float hi = src[(2 * k2 + 1) * H + nn];
            wp[i] = pack_h2(lo, hi);
        }
    } else if (b < wpb + 8) {
        int b2 = b - wpb;
        if (tid < H) {
            int t = b2 & 3;
            const float* W = (b2 < 4) ? Wout : Wroot;
            float acc = 0.f;
            #pragma unroll 8
            for (int k = 0; k < H; k++)
                acc += emb[t * H + k] * W[k * H + tid];
            if (b2 < 4) ew[t * H + tid] = acc;
            else        er[t * H + tid] = acc;
        }
    } else {
        int i = (b - wpb - 8) * 256 + tid;
        if (i < n) meta[i] = 0ull;
    }
}

// -------- one pass over edges: packed 64-bit atomic + CSR write --------
__global__ void scatter_pad_kernel(const int* __restrict__ row, const int* __restrict__ col,
                                   const int* __restrict__ x,
                                   unsigned long long* __restrict__ meta,
                                   int* __restrict__ csr_pad, int E) {
    int e = blockIdx.x * blockDim.x + threadIdx.x;
    if (e >= E) return;
    int r = row[e], c = col[e];
    if (r != c) {
        unsigned long long v = 1ull | (1ull << ((x[r] + 1) * 8));
        unsigned long long old = atomicAdd(&meta[c], v);
        int p = (int)(old & 0xffull);
        if (p < PAD) csr_pad[(size_t)c * PAD + p] = r;
    }
}

// -------- layer 1 (rank-4 closed form, fp32 math, fp16 output) --------
__global__ __launch_bounds__(256, 4)
void layer1_kernel(const int* __restrict__ x, const unsigned long long* __restrict__ meta,
                   const float* __restrict__ ew, const float* __restrict__ er,
                   const float* __restrict__ bias,
                   unsigned* __restrict__ zhout, int n) {
    __shared__ float ews[4 * H], ers[4 * H], bs[H];
    int tid = threadIdx.x;
    for (int i = tid; i < 4 * H; i += 256) { ews[i] = ew[i]; ers[i] = er[i]; }
    if (tid < H) bs[tid] = bias[tid];
    __syncthreads();

    int node = blockIdx.x * 8 + (tid >> 5);
    if (node >= n) return;
    int l4 = (tid & 31) * 4;

    int xs = x[node];
    unsigned long long m = meta[node];
    int deg  = (int)(m & 0xffull);
    float c0 = (float)((m >> 8)  & 0xffull);
    float c1 = (float)((m >> 16) & 0xffull);
    float c2 = (float)((m >> 24) & 0xffull);
    float c3 = (float)((m >> 32) & 0xffull);
    float di = 1.0f / (float)(deg + 1);

    float o[4];
    #pragma unroll
    for (int q = 0; q < 4; q++) {
        int j = l4 + q;
        float a = ews[xs * H + j]
                + c0 * ews[j] + c1 * ews[H + j] + c2 * ews[2 * H + j] + c3 * ews[3 * H + j];
        float v = di * a + ers[xs * H + j] + bs[j];
        o[q] = fmaxf(v, 0.f);
    }
    uint2 hm;
    hm.x = pack_h2(o[0], o[1]);
    hm.y = pack_h2(o[2], o[3]);
    *(uint2*)&zhout[(size_t)node * 64 + (l4 >> 1)] = hm;
}

// -------- SpMM: warp/node, paired-neighbor uint4 gather (16-lane halves) --------
// parity p = lane/16 handles neighbors 2t+p; segment s = lane%16 covers halves [8s,8s+8).
__global__ void spmm_kernel(const unsigned* __restrict__ zh, unsigned* __restrict__ aggh,
                            const unsigned long long* __restrict__ meta,
                            const int* __restrict__ csr_pad, int n) {
    int warp = (blockIdx.x * blockDim.x + threadIdx.x) >> 5;
    int lane = threadIdx.x & 31;
    if (warp >= n) return;
    int p = lane >> 4, s = lane & 15;
    const uint4* z4 = (const uint4*)zh;

    float acc[8];
    #pragma unroll
    for (int k = 0; k < 8; k++) acc[k] = 0.f;
    if (p == 0) h8_acc(acc, z4[(size_t)warp * 16 + s]);   // self term on parity 0

    int deg = (int)(meta[warp] & 0xffull);
    int e = (deg < PAD) ? deg : PAD;
    const int* csr = csr_pad + (size_t)warp * PAD;
    const int4* c4 = (const int4*)csr;

    int i = 0;
    for (; i + 8 <= e; i += 8) {
        int4 ia = c4[i >> 2];
        int4 ib = c4[(i >> 2) + 1];
        int r0 = p ? ia.y : ia.x;
        int r1 = p ? ia.w : ia.z;
        int r2 = p ? ib.y : ib.x;
        int r3 = p ? ib.w : ib.z;
        uint4 d0 = z4[(size_t)r0 * 16 + s];
        uint4 d1 = z4[(size_t)r1 * 16 + s];
        uint4 d2 = z4[(size_t)r2 * 16 + s];
        uint4 d3 = z4[(size_t)r3 * 16 + s];
        // fp16 pairwise tree over 4 non-negative values (no cancellation)
        uint4 s01 = hadd2x4(d0, d1);
        uint4 s23 = hadd2x4(d2, d3);
        uint4 t   = hadd2x4(s01, s23);
        h8_acc(acc, t);
    }
    // tail: pairs of 2 (parity-split), then optional single on parity 0
    for (; i + 2 <= e; i += 2) {
        int r = csr[i + p];
        h8_acc(acc, z4[(size_t)r * 16 + s]);
    }
    if (i < e && p == 0) {
        int r = csr[i];
        h8_acc(acc, z4[(size_t)r * 16 + s]);
    }

    // combine parity halves (lane s gets lane s+16's partial)
    #pragma unroll
    for (int k = 0; k < 8; k++)
        acc[k] += __shfl_xor_sync(0xFFFFFFFFu, acc[k], 16);

    if (p == 0) {
        float di = 1.0f / (float)(deg + 1);
        uint4 o;
        o.x = pack_h2(acc[0] * di, acc[1] * di);
        o.y = pack_h2(acc[2] * di, acc[3] * di);
        o.z = pack_h2(acc[4] * di, acc[5] * di);
        o.w = pack_h2(acc[6] * di, acc[7] * di);
        ((uint4*)aggh)[(size_t)warp * 16 + s] = o;
    }
}

// -------- fp16 tensor-core GEMM (m16n8k16), BM=64, cp.async, occupancy 4 --------
// out = relu([A|Z](n x 256 halves) @ [W0;W1](256x128) + b)
// If pred != nullptr: fused head -> pred[r] = relu(...)·w2 + b2.
#define BM 64
#define LDAW 20
#define LDWW 136
#define ASW (BM * LDAW)
#define WSW (16 * LDWW)
#define GEMM_SMEM ((2 * ASW + 2 * WSW) * 4)   // 27648 B

__global__ __launch_bounds__(256, 4)
void gemm_h(const unsigned* __restrict__ A, const unsigned* __restrict__ Z,
            const unsigned* __restrict__ W0, const unsigned* __restrict__ W1,
            const float* __restrict__ bias, unsigned* __restrict__ out_h,
            const float* __restrict__ w2, const float* __restrict__ b2,
            const int* __restrict__ labels, float* __restrict__ pred,
            int n, int out_size)
{
    extern __shared__ unsigned sm[];
    unsigned* Asb[2] = { sm,            sm + ASW };
    unsigned* Wsb[2] = { sm + 2 * ASW,  sm + 2 * ASW + WSW };
    const uint32_t sb = smem_u32(sm);
    const uint32_t a_u32[2] = { sb,               sb + ASW * 4 };
    const uint32_t w_u32[2] = { sb + 2 * ASW * 4, sb + (2 * ASW + WSW) * 4 };

    const int tid  = threadIdx.x;
    const int lane = tid & 31;
    const int warp = tid >> 5;
    const int wm = (warp & 1) * 32;
    const int wn = (warp >> 1) * 32;
    const int gid = lane >> 2;
    const int tig = lane & 3;
    const int m0 = blockIdx.x * BM;

    auto stage = [&](int buf, int kc) {
        const unsigned* srcA = (kc < 4) ? A : Z;
        const unsigned* srcW = (kc < 4) ? W0 : W1;
        int kw = (kc & 3) * 16;
        {
            int m = tid >> 2, seg = tid & 3;
            int gm = m0 + m;
            int ok = (gm < n);
            const unsigned* g = srcA + (size_t)(ok ? gm : 0) * 64 + kw + seg * 4;
            CP_ASYNC16(a_u32[buf] + (uint32_t)(m * LDAW + seg * 4) * 4, g, ok ? 16 : 0);
        }
        #pragma unroll
        for (int ii = 0; ii < 2; ii++) {
            int idx = tid + ii * 256;
            int k2 = idx >> 5, seg = idx & 31;
            const unsigned* g = srcW + (kc & 3) * 2048 + k2 * 128 + seg * 4;
            CP_ASYNC16(w_u32[buf] + (uint32_t)(k2 * LDWW + seg * 4) * 4, g, 16);
        }
        CP_COMMIT();
    };

    float c[2][4][4];
    #pragma unroll
    for (int i = 0; i < 2; i++)
        #pragma unroll
        for (int j = 0; j < 4; j++)
            #pragma unroll
            for (int q = 0; q < 4; q++) c[i][j][q] = 0.f;

    stage(0, 0);

    #pragma unroll 1
    for (int kc = 0; kc < 8; kc++) {
        int cur = kc & 1;
        if (kc < 7) { stage(cur ^ 1, kc + 1); CP_WAIT(1); }
        else        { CP_WAIT(0); }
        __syncthreads();

        const unsigned* as = Asb[cur];
        const unsigned* ws = Wsb[cur];
        #pragma unroll
        for (int ks = 0; ks < 2; ks++) {
            int k0 = ks * 8;
            unsigned af[2][4], bf[4][2];
            #pragma unroll
            for (int i = 0; i < 2; i++) {
                int r0 = (wm + 16 * i + gid) * LDAW;
                int r1 = (wm + 16 * i + 8 + gid) * LDAW;
                af[i][0] = as[r0 + k0 + tig];
                af[i][1] = as[r1 + k0 + tig];
                af[i][2] = as[r0 + k0 + tig + 4];
                af[i][3] = as[r1 + k0 + tig + 4];
            }
            #pragma unroll
            for (int j = 0; j < 4; j++) {
                bf[j][0] = ws[(k0 + tig) * LDWW + wn + 8 * j + gid];
                bf[j][1] = ws[(k0 + tig + 4) * LDWW + wn + 8 * j + gid];
            }
            #pragma unroll
            for (int i = 0; i < 2; i++)
                #pragma unroll
                for (int j = 0; j < 4; j++)
                    mma_f16(c[i][j], af[i], bf[j]);
        }
        __syncthreads();
    }

    if (pred == nullptr) {
        // layer epilogue: bias + relu -> fp16x2
        #pragma unroll
        for (int j = 0; j < 4; j++) {
            int col = wn + 8 * j + 2 * tig;
            float b0 = bias[col], b1v = bias[col + 1];
            #pragma unroll
            for (int i = 0; i < 2; i++) {
                int r0 = m0 + wm + 16 * i + gid;
                if (r0 < n) {
                    float ox = fmaxf(c[i][j][0] + b0, 0.f);
                    float oy = fmaxf(c[i][j][1] + b1v, 0.f);
                    out_h[(size_t)r0 * 64 + (col >> 1)] = pack_h2(ox, oy);
                }
                int r1 = r0 + 8;
                if (r1 < n) {
                    float ox = fmaxf(c[i][j][2] + b0, 0.f);
                    float oy = fmaxf(c[i][j][3] + b1v, 0.f);
                    out_h[(size_t)r1 * 64 + (col >> 1)] = pack_h2(ox, oy);
                }
            }
        }
    } else {
        // fused head: per-row partial of relu(c+b1)·w2, quad shfl + smem reduce
        float part[4];
        part[0] = part[1] = part[2] = part[3] = 0.f;
        #pragma unroll
        for (int j = 0; j < 4; j++) {
            int col = wn + 8 * j + 2 * tig;
            float b0 = bias[col], b1v = bias[col + 1];
            float w0 = w2[col],  w1v = w2[col + 1];
            #pragma unroll
            for (int i = 0; i < 2; i++) {
                part[2 * i]     += fmaxf(c[i][j][0] + b0, 0.f) * w0
                                 + fmaxf(c[i][j][1] + b1v, 0.f) * w1v;
                part[2 * i + 1] += fmaxf(c[i][j][2] + b0, 0.f) * w0
                                 + fmaxf(c[i][j][3] + b1v, 0.f) * w1v;
            }
        }
        #pragma unroll
        for (int q = 0; q < 4; q++) {
            part[q] += __shfl_xor_sync(0xFFFFFFFFu, part[q], 1);
            part[q] += __shfl_xor_sync(0xFFFFFFFFu, part[q], 2);
        }
        float* red = (float*)sm;   // [64][4]
        if (tig == 0) {
            int wg = warp >> 1;
            red[(wm + gid)      * 4 + wg] = part[0];
            red[(wm + 8 + gid)  * 4 + wg] = part[1];
            red[(wm + 16 + gid) * 4 + wg] = part[2];
            red[(wm + 24 + gid) * 4 + wg] = part[3];
        }
        __syncthreads();
        if (tid < 64) {
            int r = m0 + tid;
            if (r < n) {
                float sres = red[tid * 4] + red[tid * 4 + 1] + red[tid * 4 + 2] + red[tid * 4 + 3]
                           + b2[0];
                pred[r] = sres;
                if (out_size >= 2 * n) pred[n + r] = (float)labels[r];
            }
        }
    }
}

// -------- host --------
extern "C" void kernel_launch(void* const* d_in, const int* in_sizes, int n_in,
                              void* d_out, int out_size) {
    const int*   x        = (const int*)d_in[0];
    const int*   eidx     = (const int*)d_in[2];
    const int*   labels   = (const int*)d_in[3];
    const float* node_emb = (const float*)d_in[4];
    const float* Wout     = (const float*)d_in[6];
    const float* bout     = (const float*)d_in[7];
    const float* Wroot    = (const float*)d_in[8];
    const float* w1       = (const float*)d_in[9];
    const float* b1       = (const float*)d_in[10];
    const float* w2       = (const float*)d_in[11];
    const float* b2       = (const float*)d_in[12];
    float* out = (float*)d_out;

    int n = in_sizes[0];
    int E = in_sizes[2] / 2;
    int B = in_sizes[3];
    int L = in_sizes[6] / (H * H);

    const int* row = eidx;
    const int* col = eidx + E;

    unsigned *zh1, *zh2, *aggh, *wp;
    float *ew, *er;
    unsigned long long *meta;
    int *csr;
    cudaGetSymbolAddress((void**)&zh1,  g_zh1);
    cudaGetSymbolAddress((void**)&zh2,  g_zh2);
    cudaGetSymbolAddress((void**)&aggh, g_aggh);
    cudaGetSymbolAddress((void**)&wp,   g_wp);
    cudaGetSymbolAddress((void**)&ew,   g_ew);
    cudaGetSymbolAddress((void**)&er,   g_er);
    cudaGetSymbolAddress((void**)&meta, g_meta);
    cudaGetSymbolAddress((void**)&csr,  g_csr_pad);

    int wp_total = (2 * L + 2) * 8192;
    int wpb = (wp_total + 255) / 256;
    int prep_grid = wpb + 8 + (n + 255) / 256;

    // 1) fused prep, then edge pass
    prep_kernel<<<prep_grid, 256>>>(Wout, Wroot, w1, wp, L, node_emb, ew, er, meta, n, wpb);
    scatter_pad_kernel<<<(E + 255) / 256, 256>>>(row, col, x, meta, csr, E);

    // 2) layer 1 (closed form, rank-4)
    layer1_kernel<<<(n + 7) / 8, 256>>>(x, meta, ew, er, bout, zh1, n);

    // 3) layers 2..L: spmm + fp16 tc-gemm, ping-pong zh1/zh2
    int spmm_grid = (n * 32 + 63) / 64;
    int gemm_grid = (n + BM - 1) / BM;
    unsigned* zin  = zh1;
    unsigned* zout = zh2;
    for (int l = 1; l < L; l++) {
        spmm_kernel<<<spmm_grid, 64>>>(zin, aggh, meta, csr, n);
        gemm_h<<<gemm_grid, 256, GEMM_SMEM>>>(aggh, zin,
                                              wp + (size_t)l * 8192,
                                              wp + (size_t)(L + l) * 8192,
                                              bout + (size_t)l * H, zout,
                                              nullptr, nullptr, nullptr, nullptr,
                                              n, 0);
        unsigned* t = zin; zin = zout; zout = t;
    }

    // 4) fused head: [z_r | z_{B+r}] @ w1 (+b1, relu) · w2 + b2 -> pred, + labels
    int head_grid = (B + BM - 1) / BM;
    gemm_h<<<head_grid, 256, GEMM_SMEM>>>(zin, zin + (size_t)B * 64,
                                          wp + (size_t)(2 * L) * 8192,
                                          wp + (size_t)(2 * L + 1) * 8192,
                                          b1, nullptr,
                                          w2, b2, labels, out,
                                          B, out_size);
}

// round 16
// speedup vs baseline: 1.0086x; 1.0086x over previous
#include <cuda_runtime.h>
#include <cuda_fp16.h>
#include <cstdio>
#include <cstdint>

#define N_MAX 50000
#define E_MAX 800000
#define H 128
#define PAD 80

// -------- scratch (device globals; no allocation allowed) --------
__device__ unsigned           g_zh1[(size_t)N_MAX * 64];   // fp16x2 layer-1 out
__device__ unsigned           g_zh2[(size_t)N_MAX * 64];   // fp16x2 layer-2 out
__device__ unsigned           g_aggh[(size_t)N_MAX * 64];  // fp16x2 aggregated
__device__ unsigned           g_wp[8 * 8192];              // half2-packed weights [(2L+2) x 64 x 128]
__device__ float              g_ew[4 * H];
__device__ float              g_er[4 * H];
__device__ int                g_csr_pad[(size_t)N_MAX * PAD];
__device__ unsigned long long g_meta[N_MAX];   // [0:8)=deg, [8:16)=cnt0 ... [32:40)=cnt3

// -------- helpers --------
__device__ __forceinline__ uint32_t pack_h2(float lo, float hi) {
    __half2 h = __floats2half2_rn(lo, hi);
    return *reinterpret_cast<uint32_t*>(&h);
}
__device__ __forceinline__ float4 h4_to_f4(uint2 v) {
    __half2 a = *reinterpret_cast<__half2*>(&v.x);
    __half2 b = *reinterpret_cast<__half2*>(&v.y);
    float2 fa = __half22float2(a);
    float2 fb = __half22float2(b);
    return make_float4(fa.x, fa.y, fb.x, fb.y);
}
__device__ __forceinline__ uint32_t hadd2u(uint32_t a, uint32_t b) {
    uint32_t r;
    asm("add.rn.f16x2 %0, %1, %2;" : "=r"(r) : "r"(a), "r"(b));
    return r;
}

__device__ __forceinline__ void mma_f16(float c[4], const unsigned a[4], const unsigned b[2]) {
    asm volatile(
        "mma.sync.aligned.m16n8k16.row.col.f32.f16.f16.f32 "
        "{%0,%1,%2,%3}, {%4,%5,%6,%7}, {%8,%9}, {%0,%1,%2,%3};\n"
        : "+f"(c[0]), "+f"(c[1]), "+f"(c[2]), "+f"(c[3])
        : "r"(a[0]), "r"(a[1]), "r"(a[2]), "r"(a[3]), "r"(b[0]), "r"(b[1]));
}

__device__ __forceinline__ uint32_t smem_u32(const void* p) {
    uint32_t a;
    asm("{ .reg .u64 t; cvta.to.shared.u64 t, %1; cvt.u32.u64 %0, t; }" : "=r"(a) : "l"(p));
    return a;
}
#define CP_ASYNC16(dst_u32, src_ptr, szbytes) \
    asm volatile("cp.async.cg.shared.global [%0], [%1], 16, %2;" \
        :: "r"(dst_u32), "l"(src_ptr), "r"(szbytes))
#define CP_COMMIT() asm volatile("cp.async.commit_group;" ::: "memory")
#define CP_WAIT(nn)  asm volatile("cp.async.wait_group %0;" :: "n"(nn) : "memory")

// -------- fused prep: [0,wpb) pack weights | [wpb,wpb+8) EW/ER | rest zero meta --------
__global__ void prep_kernel(const float* __restrict__ Wout, const float* __restrict__ Wroot,
                            const float* __restrict__ w1,
                            unsigned* __restrict__ wp, int L,
                            const float* __restrict__ emb,
                            float* __restrict__ ew, float* __restrict__ er,
                            unsigned long long* __restrict__ meta,
                            int n, int wpb) {
    int b = blockIdx.x;
    int tid = threadIdx.x;
    if (b < wpb) {
        int i = b * 256 + tid;
        int total = (2 * L + 2) * 8192;
        if (i < total) {
            int m  = i >> 13;
            int w  = i & 8191;
            int k2 = w >> 7;
            int nn = w & 127;
            const float* src;
            if (m < L)           src = Wout + (size_t)m * (H * H);
            else if (m < 2 * L)  src = Wroot + (size_t)(m - L) * (H * H);
            else if (m == 2 * L) src = w1;
            else                 src = w1 + (size_t)H * H;
            float lo = src[(2 * k2) * H + nn];
            float hi = src[(2 * k2 + 1) * H + nn];
            wp[i] = pack_h2(lo, hi);
        }
    } else if (b < wpb + 8) {
        int b2 = b - wpb;
        if (tid < H) {
            int t = b2 & 3;
            const float* W = (b2 < 4) ? Wout : Wroot;
            float acc = 0.f;
            #pragma unroll 8
            for (int k = 0; k < H; k++)
                acc += emb[t * H + k] * W[k * H + tid];
            if (b2 < 4) ew[t * H + tid] = acc;
            else        er[t * H + tid] = acc;
        }
    } else {
        int i = (b - wpb - 8) * 256 + tid;
        if (i < n) meta[i] = 0ull;
    }
}

// -------- edge pass: 4 edges/thread, int4 loads, 4 independent packed atomics --------
__global__ void scatter_pad_kernel(const int* __restrict__ row, const int* __restrict__ col,
                                   const int* __restrict__ x,
                                   unsigned long long* __restrict__ meta,
                                   int* __restrict__ csr_pad, int E) {
    int t = blockIdx.x * blockDim.x + threadIdx.x;
    int base = t * 4;
    if (base >= E) return;

    int r[4], c[4];
    if (base + 4 <= E) {
        int4 r4 = *(const int4*)(row + base);
        int4 c4 = *(const int4*)(col + base);
        r[0] = r4.x; r[1] = r4.y; r[2] = r4.z; r[3] = r4.w;
        c[0] = c4.x; c[1] = c4.y; c[2] = c4.z; c[3] = c4.w;
    } else {
        #pragma unroll
        for (int k = 0; k < 4; k++) {
            int e = base + k;
            r[k] = (e < E) ? row[e] : 0;
            c[k] = (e < E) ? col[e] : 0;
        }
    }
    int nvalid = (base + 4 <= E) ? 4 : (E - base);

    // independent x gathers (overlapped)
    int xv[4];
    #pragma unroll
    for (int k = 0; k < 4; k++)
        xv[k] = (k < nvalid && r[k] != c[k]) ? x[r[k]] : -1;

    // independent atomic chains (4-deep MLP on atomic returns)
    #pragma unroll
    for (int k = 0; k < 4; k++) {
        if (xv[k] >= 0) {
            unsigned long long v = 1ull | (1ull << ((xv[k] + 1) * 8));
            unsigned long long old = atomicAdd(&meta[c[k]], v);
            int p = (int)(old & 0xffull);
            if (p < PAD) csr_pad[(size_t)c[k] * PAD + p] = r[k];
        }
    }
}

// -------- layer 1 (rank-4 closed form, fp32 math, fp16 output) --------
__global__ __launch_bounds__(256, 4)
void layer1_kernel(const int* __restrict__ x, const unsigned long long* __restrict__ meta,
                   const float* __restrict__ ew, const float* __restrict__ er,
                   const float* __restrict__ bias,
                   unsigned* __restrict__ zhout, int n) {
    __shared__ float ews[4 * H], ers[4 * H], bs[H];
    int tid = threadIdx.x;
    for (int i = tid; i < 4 * H; i += 256) { ews[i] = ew[i]; ers[i] = er[i]; }
    if (tid < H) bs[tid] = bias[tid];
    __syncthreads();

    int node = blockIdx.x * 8 + (tid >> 5);
    if (node >= n) return;
    int l4 = (tid & 31) * 4;

    int xs = x[node];
    unsigned long long m = meta[node];
    int deg  = (int)(m & 0xffull);
    float c0 = (float)((m >> 8)  & 0xffull);
    float c1 = (float)((m >> 16) & 0xffull);
    float c2 = (float)((m >> 24) & 0xffull);
    float c3 = (float)((m >> 32) & 0xffull);
    float di = 1.0f / (float)(deg + 1);

    float o[4];
    #pragma unroll
    for (int q = 0; q < 4; q++) {
        int j = l4 + q;
        float a = ews[xs * H + j]
                + c0 * ews[j] + c1 * ews[H + j] + c2 * ews[2 * H + j] + c3 * ews[3 * H + j];
        float v = di * a + ers[xs * H + j] + bs[j];
        o[q] = fmaxf(v, 0.f);
    }
    uint2 hm;
    hm.x = pack_h2(o[0], o[1]);
    hm.y = pack_h2(o[2], o[3]);
    *(uint2*)&zhout[(size_t)node * 64 + (l4 >> 1)] = hm;
}

// -------- SpMM (R14 form): 64-thread CTAs, int4 index loads, HADD2 pairwise + fp32 acc --------
__global__ void spmm_kernel(const unsigned* __restrict__ zh, unsigned* __restrict__ aggh,
                            const unsigned long long* __restrict__ meta,
                            const int* __restrict__ csr_pad, int n) {
    int warp = (blockIdx.x * blockDim.x + threadIdx.x) >> 5;
    int lane = threadIdx.x & 31;
    if (warp >= n) return;
    const uint2* z2 = (const uint2*)zh;
    float4 acc = h4_to_f4(z2[(size_t)warp * 32 + lane]);
    int deg = (int)(meta[warp] & 0xffull);
    int e = (deg < PAD) ? deg : PAD;
    const int* csr = csr_pad + (size_t)warp * PAD;
    const int4* c4 = (const int4*)csr;
    int i = 0;
    for (; i + 8 <= e; i += 8) {
        int4 ia = c4[i >> 2];
        int4 ib = c4[(i >> 2) + 1];
        uint2 d0 = z2[(size_t)ia.x * 32 + lane];
        uint2 d1 = z2[(size_t)ia.y * 32 + lane];
        uint2 d2 = z2[(size_t)ia.z * 32 + lane];
        uint2 d3 = z2[(size_t)ia.w * 32 + lane];
        uint2 d4 = z2[(size_t)ib.x * 32 + lane];
        uint2 d5 = z2[(size_t)ib.y * 32 + lane];
        uint2 d6 = z2[(size_t)ib.z * 32 + lane];
        uint2 d7 = z2[(size_t)ib.w * 32 + lane];
        uint2 s01 = make_uint2(hadd2u(d0.x, d1.x), hadd2u(d0.y, d1.y));
        uint2 s23 = make_uint2(hadd2u(d2.x, d3.x), hadd2u(d2.y, d3.y));
        uint2 s45 = make_uint2(hadd2u(d4.x, d5.x), hadd2u(d4.y, d5.y));
        uint2 s67 = make_uint2(hadd2u(d6.x, d7.x), hadd2u(d6.y, d7.y));
        float4 f0 = h4_to_f4(s01);
        float4 f1 = h4_to_f4(s23);
        float4 f2 = h4_to_f4(s45);
        float4 f3 = h4_to_f4(s67);
        acc.x += (f0.x + f1.x) + (f2.x + f3.x);
        acc.y += (f0.y + f1.y) + (f2.y + f3.y);
        acc.z += (f0.z + f1.z) + (f2.z + f3.z);
        acc.w += (f0.w + f1.w) + (f2.w + f3.w);
    }
    for (; i < e; i++) {
        int r = csr[i];
        float4 v = h4_to_f4(z2[(size_t)r * 32 + lane]);
        acc.x += v.x; acc.y += v.y; acc.z += v.z; acc.w += v.w;
    }
    float di = 1.0f / (float)(deg + 1);
    uint2 o;
    o.x = pack_h2(acc.x * di, acc.y * di);
    o.y = pack_h2(acc.z * di, acc.w * di);
    ((uint2*)aggh)[(size_t)warp * 32 + lane] = o;
}

// -------- fp16 tensor-core GEMM (m16n8k16), BM=64, cp.async, occupancy 4 --------
// out = relu([A|Z](n x 256 halves) @ [W0;W1](256x128) + b)
// If pred != nullptr: fused head -> pred[r] = relu(...)·w2 + b2.
#define BM 64
#define LDAW 20
#define LDWW 136
#define ASW (BM * LDAW)
#define WSW (16 * LDWW)
#define GEMM_SMEM ((2 * ASW + 2 * WSW) * 4)   // 27648 B

__global__ __launch_bounds__(256, 4)
void gemm_h(const unsigned* __restrict__ A, const unsigned* __restrict__ Z,
            const unsigned* __restrict__ W0, const unsigned* __restrict__ W1,
            const float* __restrict__ bias, unsigned* __restrict__ out_h,
            const float* __restrict__ w2, const float* __restrict__ b2,
            const int* __restrict__ labels, float* __restrict__ pred,
            int n, int out_size)
{
    extern __shared__ unsigned sm[];
    unsigned* Asb[2] = { sm,            sm + ASW };
    unsigned* Wsb[2] = { sm + 2 * ASW,  sm + 2 * ASW + WSW };
    const uint32_t sb = smem_u32(sm);
    const uint32_t a_u32[2] = { sb,               sb + ASW * 4 };
    const uint32_t w_u32[2] = { sb + 2 * ASW * 4, sb + (2 * ASW + WSW) * 4 };

    const int tid  = threadIdx.x;
    const int lane = tid & 31;
    const int warp = tid >> 5;
    const int wm = (warp & 1) * 32;
    const int wn = (warp >> 1) * 32;
    const int gid = lane >> 2;
    const int tig = lane & 3;
    const int m0 = blockIdx.x * BM;

    auto stage = [&](int buf, int kc) {
        const unsigned* srcA = (kc < 4) ? A : Z;
        const unsigned* srcW = (kc < 4) ? W0 : W1;
        int kw = (kc & 3) * 16;
        {
            int m = tid >> 2, seg = tid & 3;
            int gm = m0 + m;
            int ok = (gm < n);
            const unsigned* g = srcA + (size_t)(ok ? gm : 0) * 64 + kw + seg * 4;
            CP_ASYNC16(a_u32[buf] + (uint32_t)(m * LDAW + seg * 4) * 4, g, ok ? 16 : 0);
        }
        #pragma unroll
        for (int ii = 0; ii < 2; ii++) {
            int idx = tid + ii * 256;
            int k2 = idx >> 5, seg = idx & 31;
            const unsigned* g = srcW + (kc & 3) * 2048 + k2 * 128 + seg * 4;
            CP_ASYNC16(w_u32[buf] + (uint32_t)(k2 * LDWW + seg * 4) * 4, g, 16);
        }
        CP_COMMIT();
    };

    float c[2][4][4];
    #pragma unroll
    for (int i = 0; i < 2; i++)
        #pragma unroll
        for (int j = 0; j < 4; j++)
            #pragma unroll
            for (int q = 0; q < 4; q++) c[i][j][q] = 0.f;

    stage(0, 0);

    #pragma unroll 1
    for (int kc = 0; kc < 8; kc++) {
        int cur = kc & 1;
        if (kc < 7) { stage(cur ^ 1, kc + 1); CP_WAIT(1); }
        else        { CP_WAIT(0); }
        __syncthreads();

        const unsigned* as = Asb[cur];
        const unsigned* ws = Wsb[cur];
        #pragma unroll
        for (int ks = 0; ks < 2; ks++) {
            int k0 = ks * 8;
            unsigned af[2][4], bf[4][2];
            #pragma unroll
            for (int i = 0; i < 2; i++) {
                int r0 = (wm + 16 * i + gid) * LDAW;
                int r1 = (wm + 16 * i + 8 + gid) * LDAW;
                af[i][0] = as[r0 + k0 + tig];
                af[i][1] = as[r1 + k0 + tig];
                af[i][2] = as[r0 + k0 + tig + 4];
                af[i][3] = as[r1 + k0 + tig + 4];
            }
            #pragma unroll
            for (int j = 0; j < 4; j++) {
                bf[j][0] = ws[(k0 + tig) * LDWW + wn + 8 * j + gid];
                bf[j][1] = ws[(k0 + tig + 4) * LDWW + wn + 8 * j + gid];
            }
            #pragma unroll
            for (int i = 0; i < 2; i++)
                #pragma unroll
                for (int j = 0; j < 4; j++)
                    mma_f16(c[i][j], af[i], bf[j]);
        }
        __syncthreads();
    }

    if (pred == nullptr) {
        // layer epilogue: bias + relu -> fp16x2
        #pragma unroll
        for (int j = 0; j < 4; j++) {
            int col = wn + 8 * j + 2 * tig;
            float b0 = bias[col], b1v = bias[col + 1];
            #pragma unroll
            for (int i = 0; i < 2; i++) {
                int r0 = m0 + wm + 16 * i + gid;
                if (r0 < n) {
                    float ox = fmaxf(c[i][j][0] + b0, 0.f);
                    float oy = fmaxf(c[i][j][1] + b1v, 0.f);
                    out_h[(size_t)r0 * 64 + (col >> 1)] = pack_h2(ox, oy);
                }
                int r1 = r0 + 8;
                if (r1 < n) {
                    float ox = fmaxf(c[i][j][2] + b0, 0.f);
                    float oy = fmaxf(c[i][j][3] + b1v, 0.f);
                    out_h[(size_t)r1 * 64 + (col >> 1)] = pack_h2(ox, oy);
                }
            }
        }
    } else {
        // fused head: per-row partial of relu(c+b1)·w2, quad shfl + smem reduce
        float part[4];
        part[0] = part[1] = part[2] = part[3] = 0.f;
        #pragma unroll
        for (int j = 0; j < 4; j++) {
            int col = wn + 8 * j + 2 * tig;
            float b0 = bias[col], b1v = bias[col + 1];
            float w0 = w2[col],  w1v = w2[col + 1];
            #pragma unroll
            for (int i = 0; i < 2; i++) {
                part[2 * i]     += fmaxf(c[i][j][0] + b0, 0.f) * w0
                                 + fmaxf(c[i][j][1] + b1v, 0.f) * w1v;
                part[2 * i + 1] += fmaxf(c[i][j][2] + b0, 0.f) * w0
                                 + fmaxf(c[i][j][3] + b1v, 0.f) * w1v;
            }
        }
        #pragma unroll
        for (int q = 0; q < 4; q++) {
            part[q] += __shfl_xor_sync(0xFFFFFFFFu, part[q], 1);
            part[q] += __shfl_xor_sync(0xFFFFFFFFu, part[q], 2);
        }
        float* red = (float*)sm;   // [64][4]
        if (tig == 0) {
            int wg = warp >> 1;
            red[(wm + gid)      * 4 + wg] = part[0];
            red[(wm + 8 + gid)  * 4 + wg] = part[1];
            red[(wm + 16 + gid) * 4 + wg] = part[2];
            red[(wm + 24 + gid) * 4 + wg] = part[3];
        }
        __syncthreads();
        if (tid < 64) {
            int r = m0 + tid;
            if (r < n) {
                float sres = red[tid * 4] + red[tid * 4 + 1] + red[tid * 4 + 2] + red[tid * 4 + 3]
                           + b2[0];
                pred[r] = sres;
                if (out_size >= 2 * n) pred[n + r] = (float)labels[r];
            }
        }
    }
}

// -------- host --------
extern "C" void kernel_launch(void* const* d_in, const int* in_sizes, int n_in,
                              void* d_out, int out_size) {
    const int*   x        = (const int*)d_in[0];
    const int*   eidx     = (const int*)d_in[2];
    const int*   labels   = (const int*)d_in[3];
    const float* node_emb = (const float*)d_in[4];
    const float* Wout     = (const float*)d_in[6];
    const float* bout     = (const float*)d_in[7];
    const float* Wroot    = (const float*)d_in[8];
    const float* w1       = (const float*)d_in[9];
    const float* b1       = (const float*)d_in[10];
    const float* w2       = (const float*)d_in[11];
    const float* b2       = (const float*)d_in[12];
    float* out = (float*)d_out;

    int n = in_sizes[0];
    int E = in_sizes[2] / 2;
    int B = in_sizes[3];
    int L = in_sizes[6] / (H * H);

    const int* row = eidx;
    const int* col = eidx + E;

    unsigned *zh1, *zh2, *aggh, *wp;
    float *ew, *er;
    unsigned long long *meta;
    int *csr;
    cudaGetSymbolAddress((void**)&zh1,  g_zh1);
    cudaGetSymbolAddress((void**)&zh2,  g_zh2);
    cudaGetSymbolAddress((void**)&aggh, g_aggh);
    cudaGetSymbolAddress((void**)&wp,   g_wp);
    cudaGetSymbolAddress((void**)&ew,   g_ew);
    cudaGetSymbolAddress((void**)&er,   g_er);
    cudaGetSymbolAddress((void**)&meta, g_meta);
    cudaGetSymbolAddress((void**)&csr,  g_csr_pad);

    int wp_total = (2 * L + 2) * 8192;
    int wpb = (wp_total + 255) / 256;
    int prep_grid = wpb + 8 + (n + 255) / 256;

    // 1) fused prep, then edge pass (4 edges/thread)
    prep_kernel<<<prep_grid, 256>>>(Wout, Wroot, w1, wp, L, node_emb, ew, er, meta, n, wpb);
    int ethreads = (E + 3) / 4;
    scatter_pad_kernel<<<(ethreads + 255) / 256, 256>>>(row, col, x, meta, csr, E);

    // 2) layer 1 (closed form, rank-4)
    layer1_kernel<<<(n + 7) / 8, 256>>>(x, meta, ew, er, bout, zh1, n);

    // 3) layers 2..L: spmm + fp16 tc-gemm, ping-pong zh1/zh2
    int spmm_grid = (n * 32 + 63) / 64;
    int gemm_grid = (n + BM - 1) / BM;
    unsigned* zin  = zh1;
    unsigned* zout = zh2;
    for (int l = 1; l < L; l++) {
        spmm_kernel<<<spmm_grid, 64>>>(zin, aggh, meta, csr, n);
        gemm_h<<<gemm_grid, 256, GEMM_SMEM>>>(aggh, zin,
                                              wp + (size_t)l * 8192,
                                              wp + (size_t)(L + l) * 8192,
                                              bout + (size_t)l * H, zout,
                                              nullptr, nullptr, nullptr, nullptr,
                                              n, 0);
        unsigned* t = zin; zin = zout; zout = t;
    }

    // 4) fused head: [z_r | z_{B+r}] @ w1 (+b1, relu) · w2 + b2 -> pred, + labels
    int head_grid = (B + BM - 1) / BM;
    gemm_h<<<head_grid, 256, GEMM_SMEM>>>(zin, zin + (size_t)B * 64,
                                          wp + (size_t)(2 * L) * 8192,
                                          wp + (size_t)(2 * L + 1) * 8192,
                                          b1, nullptr,
                                          w2, b2, labels, out,
                                          B, out_size);
}

// round 17
// speedup vs baseline: 1.0327x; 1.0240x over previous
#include <cuda_runtime.h>
#include <cuda_fp16.h>
#include <cstdio>
#include <cstdint>

#define N_MAX 50000
#define E_MAX 800000
#define H 128
#define PAD 80

// -------- scratch (device globals; no allocation allowed) --------
__device__ unsigned           g_zh1[(size_t)N_MAX * 64];   // fp16x2 layer-1 out
__device__ unsigned           g_zh2[(size_t)N_MAX * 64];   // fp16x2 layer-2 out
__device__ unsigned           g_aggh[(size_t)N_MAX * 64];  // fp16x2 aggregated
__device__ unsigned           g_wp[8 * 8192];              // half2-packed weights
__device__ unsigned           g_xp[(N_MAX + 15) / 16];     // 2-bit packed node types
__device__ float              g_ew[4 * H];
__device__ float              g_er[4 * H];
__device__ int                g_csr_pad[(size_t)N_MAX * PAD];
__device__ unsigned long long g_meta[N_MAX];   // [0:8)=deg, [8:16)=cnt0 ... [32:40)=cnt3

// -------- helpers --------
__device__ __forceinline__ uint32_t pack_h2(float lo, float hi) {
    __half2 h = __floats2half2_rn(lo, hi);
    return *reinterpret_cast<uint32_t*>(&h);
}
__device__ __forceinline__ float4 h4_to_f4(uint2 v) {
    __half2 a = *reinterpret_cast<__half2*>(&v.x);
    __half2 b = *reinterpret_cast<__half2*>(&v.y);
    float2 fa = __half22float2(a);
    float2 fb = __half22float2(b);
    return make_float4(fa.x, fa.y, fb.x, fb.y);
}
__device__ __forceinline__ uint32_t hadd2u(uint32_t a, uint32_t b) {
    uint32_t r;
    asm("add.rn.f16x2 %0, %1, %2;" : "=r"(r) : "r"(a), "r"(b));
    return r;
}

__device__ __forceinline__ void mma_f16(float c[4], const unsigned a[4], const unsigned b[2]) {
    asm volatile(
        "mma.sync.aligned.m16n8k16.row.col.f32.f16.f16.f32 "
        "{%0,%1,%2,%3}, {%4,%5,%6,%7}, {%8,%9}, {%0,%1,%2,%3};\n"
        : "+f"(c[0]), "+f"(c[1]), "+f"(c[2]), "+f"(c[3])
        : "r"(a[0]), "r"(a[1]), "r"(a[2]), "r"(a[3]), "r"(b[0]), "r"(b[1]));
}

__device__ __forceinline__ uint32_t smem_u32(const void* p) {
    uint32_t a;
    asm("{ .reg .u64 t; cvta.to.shared.u64 t, %1; cvt.u32.u64 %0, t; }" : "=r"(a) : "l"(p));
    return a;
}
#define CP_ASYNC16(dst_u32, src_ptr, szbytes) \
    asm volatile("cp.async.cg.shared.global [%0], [%1], 16, %2;" \
        :: "r"(dst_u32), "l"(src_ptr), "r"(szbytes))
#define CP_COMMIT() asm volatile("cp.async.commit_group;" ::: "memory")
#define CP_WAIT(nn)  asm volatile("cp.async.wait_group %0;" :: "n"(nn) : "memory")

// -------- fused prep: weights | EW/ER | zero meta | pack x (2-bit) --------
__global__ void prep_kernel(const float* __restrict__ Wout, const float* __restrict__ Wroot,
                            const float* __restrict__ w1,
                            unsigned* __restrict__ wp, int L,
                            const float* __restrict__ emb,
                            float* __restrict__ ew, float* __restrict__ er,
                            unsigned long long* __restrict__ meta,
                            const int* __restrict__ x, unsigned* __restrict__ xp,
                            int n, int wpb, int metab) {
    int b = blockIdx.x;
    int tid = threadIdx.x;
    if (b < wpb) {
        int i = b * 256 + tid;
        int total = (2 * L + 2) * 8192;
        if (i < total) {
            int m  = i >> 13;
            int w  = i & 8191;
            int k2 = w >> 7;
            int nn = w & 127;
            const float* src;
            if (m < L)           src = Wout + (size_t)m * (H * H);
            else if (m < 2 * L)  src = Wroot + (size_t)(m - L) * (H * H);
            else if (m == 2 * L) src = w1;
            else                 src = w1 + (size_t)H * H;
            float lo = src[(2 * k2) * H + nn];
            float hi = src[(2 * k2 + 1) * H + nn];
            wp[i] = pack_h2(lo, hi);
        }
    } else if (b < wpb + 8) {
        int b2 = b - wpb;
        if (tid < H) {
            int t = b2 & 3;
            const float* W = (b2 < 4) ? Wout : Wroot;
            float acc = 0.f;
            #pragma unroll 8
            for (int k = 0; k < H; k++)
                acc += emb[t * H + k] * W[k * H + tid];
            if (b2 < 4) ew[t * H + tid] = acc;
            else        er[t * H + tid] = acc;
        }
    } else if (b < wpb + 8 + metab) {
        int i = (b - wpb - 8) * 256 + tid;
        if (i < n) meta[i] = 0ull;
    } else {
        // pack 16 node types per uint32
        int wi = (b - wpb - 8 - metab) * 256 + tid;
        int nw = (n + 15) / 16;
        if (wi < nw) {
            unsigned v = 0;
            int base = wi * 16;
            #pragma unroll
            for (int k = 0; k < 16; k++) {
                int node = base + k;
                unsigned xv = (node < n) ? (unsigned)x[node] : 0u;
                v |= (xv & 3u) << (k * 2);
            }
            xp[wi] = v;
        }
    }
}

// -------- edge pass: 4 edges/thread, packed-x lookup, 4 independent packed atomics --------
__global__ void scatter_pad_kernel(const int* __restrict__ row, const int* __restrict__ col,
                                   const unsigned* __restrict__ xp,
                                   unsigned long long* __restrict__ meta,
                                   int* __restrict__ csr_pad, int E) {
    int t = blockIdx.x * blockDim.x + threadIdx.x;
    int base = t * 4;
    if (base >= E) return;

    int r[4], c[4];
    if (base + 4 <= E) {
        int4 r4 = *(const int4*)(row + base);
        int4 c4 = *(const int4*)(col + base);
        r[0] = r4.x; r[1] = r4.y; r[2] = r4.z; r[3] = r4.w;
        c[0] = c4.x; c[1] = c4.y; c[2] = c4.z; c[3] = c4.w;
    } else {
        #pragma unroll
        for (int k = 0; k < 4; k++) {
            int e = base + k;
            r[k] = (e < E) ? row[e] : 0;
            c[k] = (e < E) ? col[e] : 0;
        }
    }
    int nvalid = (base + 4 <= E) ? 4 : (E - base);

    // node type from 12.5 KB L1-resident packed table
    int xv[4];
    #pragma unroll
    for (int k = 0; k < 4; k++) {
        if (k < nvalid && r[k] != c[k])
            xv[k] = (int)((xp[r[k] >> 4] >> ((r[k] & 15) * 2)) & 3u);
        else
            xv[k] = -1;
    }

    #pragma unroll
    for (int k = 0; k < 4; k++) {
        if (xv[k] >= 0) {
            unsigned long long v = 1ull | (1ull << ((xv[k] + 1) * 8));
            unsigned long long old = atomicAdd(&meta[c[k]], v);
            int p = (int)(old & 0xffull);
            if (p < PAD) csr_pad[(size_t)c[k] * PAD + p] = r[k];
        }
    }
}

// -------- layer 1 (rank-4 closed form, fp32 math, fp16 output) --------
__global__ __launch_bounds__(256, 4)
void layer1_kernel(const int* __restrict__ x, const unsigned long long* __restrict__ meta,
                   const float* __restrict__ ew, const float* __restrict__ er,
                   const float* __restrict__ bias,
                   unsigned* __restrict__ zhout, int n) {
    __shared__ float ews[4 * H], ers[4 * H], bs[H];
    int tid = threadIdx.x;
    for (int i = tid; i < 4 * H; i += 256) { ews[i] = ew[i]; ers[i] = er[i]; }
    if (tid < H) bs[tid] = bias[tid];
    __syncthreads();

    int node = blockIdx.x * 8 + (tid >> 5);
    if (node >= n) return;
    int l4 = (tid & 31) * 4;

    int xs = x[node];
    unsigned long long m = meta[node];
    int deg  = (int)(m & 0xffull);
    float c0 = (float)((m >> 8)  & 0xffull);
    float c1 = (float)((m >> 16) & 0xffull);
    float c2 = (float)((m >> 24) & 0xffull);
    float c3 = (float)((m >> 32) & 0xffull);
    float di = 1.0f / (float)(deg + 1);

    float o[4];
    #pragma unroll
    for (int q = 0; q < 4; q++) {
        int j = l4 + q;
        float a = ews[xs * H + j]
                + c0 * ews[j] + c1 * ews[H + j] + c2 * ews[2 * H + j] + c3 * ews[3 * H + j];
        float v = di * a + ers[xs * H + j] + bs[j];
        o[q] = fmaxf(v, 0.f);
    }
    uint2 hm;
    hm.x = pack_h2(o[0], o[1]);
    hm.y = pack_h2(o[2], o[3]);
    *(uint2*)&zhout[(size_t)node * 64 + (l4 >> 1)] = hm;
}

// -------- SpMM: 64-thread CTAs, int4 idx loads, quad-level HADD2 tree + fp32 acc --------
__global__ void spmm_kernel(const unsigned* __restrict__ zh, unsigned* __restrict__ aggh,
                            const unsigned long long* __restrict__ meta,
                            const int* __restrict__ csr_pad, int n) {
    int warp = (blockIdx.x * blockDim.x + threadIdx.x) >> 5;
    int lane = threadIdx.x & 31;
    if (warp >= n) return;
    const uint2* z2 = (const uint2*)zh;
    float4 acc = h4_to_f4(z2[(size_t)warp * 32 + lane]);
    int deg = (int)(meta[warp] & 0xffull);
    int e = (deg < PAD) ? deg : PAD;
    const int* csr = csr_pad + (size_t)warp * PAD;
    const int4* c4 = (const int4*)csr;
    int i = 0;
    for (; i + 8 <= e; i += 8) {
        int4 ia = c4[i >> 2];
        int4 ib = c4[(i >> 2) + 1];
        uint2 d0 = z2[(size_t)ia.x * 32 + lane];
        uint2 d1 = z2[(size_t)ia.y * 32 + lane];
        uint2 d2 = z2[(size_t)ia.z * 32 + lane];
        uint2 d3 = z2[(size_t)ia.w * 32 + lane];
        uint2 d4 = z2[(size_t)ib.x * 32 + lane];
        uint2 d5 = z2[(size_t)ib.y * 32 + lane];
        uint2 d6 = z2[(size_t)ib.z * 32 + lane];
        uint2 d7 = z2[(size_t)ib.w * 32 + lane];
        // fp16 tree: pairs then quads (non-negative relu outputs, no cancellation;
        // quad-depth numerics validated in R15: rel_err 4.25e-4)
        uint2 s01 = make_uint2(hadd2u(d0.x, d1.x), hadd2u(d0.y, d1.y));
        uint2 s23 = make_uint2(hadd2u(d2.x, d3.x), hadd2u(d2.y, d3.y));
        uint2 s45 = make_uint2(hadd2u(d4.x, d5.x), hadd2u(d4.y, d5.y));
        uint2 s67 = make_uint2(hadd2u(d6.x, d7.x), hadd2u(d6.y, d7.y));
        uint2 q0 = make_uint2(hadd2u(s01.x, s23.x), hadd2u(s01.y, s23.y));
        uint2 q1 = make_uint2(hadd2u(s45.x, s67.x), hadd2u(s45.y, s67.y));
        float4 f0 = h4_to_f4(q0);
        float4 f1 = h4_to_f4(q1);
        acc.x += f0.x + f1.x;
        acc.y += f0.y + f1.y;
        acc.z += f0.z + f1.z;
        acc.w += f0.w + f1.w;
    }
    for (; i < e; i++) {
        int r = csr[i];
        float4 v = h4_to_f4(z2[(size_t)r * 32 + lane]);
        acc.x += v.x; acc.y += v.y; acc.z += v.z; acc.w += v.w;
    }
    float di = 1.0f / (float)(deg + 1);
    uint2 o;
    o.x = pack_h2(acc.x * di, acc.y * di);
    o.y = pack_h2(acc.z * di, acc.w * di);
    ((uint2*)aggh)[(size_t)warp * 32 + lane] = o;
}

// -------- fp16 tensor-core GEMM (m16n8k16), BM=64, cp.async, occupancy 4 --------
#define BM 64
#define LDAW 20
#define LDWW 136
#define ASW (BM * LDAW)
#define WSW (16 * LDWW)
#define GEMM_SMEM ((2 * ASW + 2 * WSW) * 4)   // 27648 B

__global__ __launch_bounds__(256, 4)
void gemm_h(const unsigned* __restrict__ A, const unsigned* __restrict__ Z,
            const unsigned* __restrict__ W0, const unsigned* __restrict__ W1,
            const float* __restrict__ bias, unsigned* __restrict__ out_h,
            const float* __restrict__ w2, const float* __restrict__ b2,
            const int* __restrict__ labels, float* __restrict__ pred,
            int n, int out_size)
{
    extern __shared__ unsigned sm[];
    unsigned* Asb[2] = { sm,            sm + ASW };
    unsigned* Wsb[2] = { sm + 2 * ASW,  sm + 2 * ASW + WSW };
    const uint32_t sb = smem_u32(sm);
    const uint32_t a_u32[2] = { sb,               sb + ASW * 4 };
    const uint32_t w_u32[2] = { sb + 2 * ASW * 4, sb + (2 * ASW + WSW) * 4 };

    const int tid  = threadIdx.x;
    const int lane = tid & 31;
    const int warp = tid >> 5;
    const int wm = (warp & 1) * 32;
    const int wn = (warp >> 1) * 32;
    const int gid = lane >> 2;
    const int tig = lane & 3;
    const int m0 = blockIdx.x * BM;

    auto stage = [&](int buf, int kc) {
        const unsigned* srcA = (kc < 4) ? A : Z;
        const unsigned* srcW = (kc < 4) ? W0 : W1;
        int kw = (kc & 3) * 16;
        {
            int m = tid >> 2, seg = tid & 3;
            int gm = m0 + m;
            int ok = (gm < n);
            const unsigned* g = srcA + (size_t)(ok ? gm : 0) * 64 + kw + seg * 4;
            CP_ASYNC16(a_u32[buf] + (uint32_t)(m * LDAW + seg * 4) * 4, g, ok ? 16 : 0);
        }
        #pragma unroll
        for (int ii = 0; ii < 2; ii++) {
            int idx = tid + ii * 256;
            int k2 = idx >> 5, seg = idx & 31;
            const unsigned* g = srcW + (kc & 3) * 2048 + k2 * 128 + seg * 4;
            CP_ASYNC16(w_u32[buf] + (uint32_t)(k2 * LDWW + seg * 4) * 4, g, 16);
        }
        CP_COMMIT();
    };

    float c[2][4][4];
    #pragma unroll
    for (int i = 0; i < 2; i++)
        #pragma unroll
        for (int j = 0; j < 4; j++)
            #pragma unroll
            for (int q = 0; q < 4; q++) c[i][j][q] = 0.f;

    stage(0, 0);

    #pragma unroll 1
    for (int kc = 0; kc < 8; kc++) {
        int cur = kc & 1;
        if (kc < 7) { stage(cur ^ 1, kc + 1); CP_WAIT(1); }
        else        { CP_WAIT(0); }
        __syncthreads();

        const unsigned* as = Asb[cur];
        const unsigned* ws = Wsb[cur];
        #pragma unroll
        for (int ks = 0; ks < 2; ks++) {
            int k0 = ks * 8;
            unsigned af[2][4], bf[4][2];
            #pragma unroll
            for (int i = 0; i < 2; i++) {
                int r0 = (wm + 16 * i + gid) * LDAW;
                int r1 = (wm + 16 * i + 8 + gid) * LDAW;
                af[i][0] = as[r0 + k0 + tig];
                af[i][1] = as[r1 + k0 + tig];
                af[i][2] = as[r0 + k0 + tig + 4];
                af[i][3] = as[r1 + k0 + tig + 4];
            }
            #pragma unroll
            for (int j = 0; j < 4; j++) {
                bf[j][0] = ws[(k0 + tig) * LDWW + wn + 8 * j + gid];
                bf[j][1] = ws[(k0 + tig + 4) * LDWW + wn + 8 * j + gid];
            }
            #pragma unroll
            for (int i = 0; i < 2; i++)
                #pragma unroll
                for (int j = 0; j < 4; j++)
                    mma_f16(c[i][j], af[i], bf[j]);
        }
        __syncthreads();
    }

    if (pred == nullptr) {
        // layer epilogue: bias + relu -> fp16x2
        #pragma unroll
        for (int j = 0; j < 4; j++) {
            int col = wn + 8 * j + 2 * tig;
            float b0 = bias[col], b1v = bias[col + 1];
            #pragma unroll
            for (int i = 0; i < 2; i++) {
                int r0 = m0 + wm + 16 * i + gid;
                if (r0 < n) {
                    float ox = fmaxf(c[i][j][0] + b0, 0.f);
                    float oy = fmaxf(c[i][j][1] + b1v, 0.f);
                    out_h[(size_t)r0 * 64 + (col >> 1)] = pack_h2(ox, oy);
                }
                int r1 = r0 + 8;
                if (r1 < n) {
                    float ox = fmaxf(c[i][j][2] + b0, 0.f);
                    float oy = fmaxf(c[i][j][3] + b1v, 0.f);
                    out_h[(size_t)r1 * 64 + (col >> 1)] = pack_h2(ox, oy);
                }
            }
        }
    } else {
        // fused head: per-row partial of relu(c+b1)·w2, quad shfl + smem reduce
        float part[4];
        part[0] = part[1] = part[2] = part[3] = 0.f;
        #pragma unroll
        for (int j = 0; j < 4; j++) {
            int col = wn + 8 * j + 2 * tig;
            float b0 = bias[col], b1v = bias[col + 1];
            float w0 = w2[col],  w1v = w2[col + 1];
            #pragma unroll
            for (int i = 0; i < 2; i++) {
                part[2 * i]     += fmaxf(c[i][j][0] + b0, 0.f) * w0
                                 + fmaxf(c[i][j][1] + b1v, 0.f) * w1v;
                part[2 * i + 1] += fmaxf(c[i][j][2] + b0, 0.f) * w0
                                 + fmaxf(c[i][j][3] + b1v, 0.f) * w1v;
            }
        }
        #pragma unroll
        for (int q = 0; q < 4; q++) {
            part[q] += __shfl_xor_sync(0xFFFFFFFFu, part[q], 1);
            part[q] += __shfl_xor_sync(0xFFFFFFFFu, part[q], 2);
        }
        float* red = (float*)sm;   // [64][4]
        if (tig == 0) {
            int wg = warp >> 1;
            red[(wm + gid)      * 4 + wg] = part[0];
            red[(wm + 8 + gid)  * 4 + wg] = part[1];
            red[(wm + 16 + gid) * 4 + wg] = part[2];
            red[(wm + 24 + gid) * 4 + wg] = part[3];
        }
        __syncthreads();
        if (tid < 64) {
            int r = m0 + tid;
            if (r < n) {
                float sres = red[tid * 4] + red[tid * 4 + 1] + red[tid * 4 + 2] + red[tid * 4 + 3]
                           + b2[0];
                pred[r] = sres;
                if (out_size >= 2 * n) pred[n + r] = (float)labels[r];
            }
        }
    }
}

// -------- host --------
extern "C" void kernel_launch(void* const* d_in, const int* in_sizes, int n_in,
                              void* d_out, int out_size) {
    const int*   x        = (const int*)d_in[0];
    const int*   eidx     = (const int*)d_in[2];
    const int*   labels   = (const int*)d_in[3];
    const float* node_emb = (const float*)d_in[4];
    const float* Wout     = (const float*)d_in[6];
    const float* bout     = (const float*)d_in[7];
    const float* Wroot    = (const float*)d_in[8];
    const float* w1       = (const float*)d_in[9];
    const float* b1       = (const float*)d_in[10];
    const float* w2       = (const float*)d_in[11];
    const float* b2       = (const float*)d_in[12];
    float* out = (float*)d_out;

    int n = in_sizes[0];
    int E = in_sizes[2] / 2;
    int B = in_sizes[3];
    int L = in_sizes[6] / (H * H);

    const int* row = eidx;
    const int* col = eidx + E;

    unsigned *zh1, *zh2, *aggh, *wp, *xp;
    float *ew, *er;
    unsigned long long *meta;
    int *csr;
    cudaGetSymbolAddress((void**)&zh1,  g_zh1);
    cudaGetSymbolAddress((void**)&zh2,  g_zh2);
    cudaGetSymbolAddress((void**)&aggh, g_aggh);
    cudaGetSymbolAddress((void**)&wp,   g_wp);
    cudaGetSymbolAddress((void**)&xp,   g_xp);
    cudaGetSymbolAddress((void**)&ew,   g_ew);
    cudaGetSymbolAddress((void**)&er,   g_er);
    cudaGetSymbolAddress((void**)&meta, g_meta);
    cudaGetSymbolAddress((void**)&csr,  g_csr_pad);

    int wp_total = (2 * L + 2) * 8192;
    int wpb = (wp_total + 255) / 256;
    int metab = (n + 255) / 256;
    int xpb = (((n + 15) / 16) + 255) / 256;
    int prep_grid = wpb + 8 + metab + xpb;

    // 1) fused prep (weights + EW/ER + meta zero + x pack), then edge pass
    prep_kernel<<<prep_grid, 256>>>(Wout, Wroot, w1, wp, L, node_emb, ew, er,
                                    meta, x, xp, n, wpb, metab);
    int ethreads = (E + 3) / 4;
    scatter_pad_kernel<<<(ethreads + 255) / 256, 256>>>(row, col, xp, meta, csr, E);

    // 2) layer 1 (closed form, rank-4)
    layer1_kernel<<<(n + 7) / 8, 256>>>(x, meta, ew, er, bout, zh1, n);

    // 3) layers 2..L: spmm + fp16 tc-gemm, ping-pong zh1/zh2
    int spmm_grid = (n * 32 + 63) / 64;
    int gemm_grid = (n + BM - 1) / BM;
    unsigned* zin  = zh1;
    unsigned* zout = zh2;
    for (int l = 1; l < L; l++) {
        spmm_kernel<<<spmm_grid, 64>>>(zin, aggh, meta, csr, n);
        gemm_h<<<gemm_grid, 256, GEMM_SMEM>>>(aggh, zin,
                                              wp + (size_t)l * 8192,
                                              wp + (size_t)(L + l) * 8192,
                                              bout + (size_t)l * H, zout,
                                              nullptr, nullptr, nullptr, nullptr,
                                              n, 0);
        unsigned* t = zin; zin = zout; zout = t;
    }

    // 4) fused head: [z_r | z_{B+r}] @ w1 (+b1, relu) · w2 + b2 -> pred, + labels
    int head_grid = (B + BM - 1) / BM;
    gemm_h<<<head_grid, 256, GEMM_SMEM>>>(zin, zin + (size_t)B * 64,
                                          wp + (size_t)(2 * L) * 8192,
                                          wp + (size_t)(2 * L + 1) * 8192,
                                          b1, nullptr,
                                          w2, b2, labels, out,
                                          B, out_size);
}